// round 2
// baseline (speedup 1.0000x reference)
#include <cuda_runtime.h>
#include <math.h>

#define BB 256
#define TT 512
#define II 256
#define HH 512
#define AA 18
#define KK (HH + II)   // 768: concat [h | x]

#define ROWS 8
#define JT   64
#define KC   64
#define STEP_THREADS 256

// ---------------- scratch (static device globals; no allocation) ----------------
__device__ float g_W[(size_t)KK * HH];            // [k][j] : k<512 -> W_hh[j][k], else W_ih[j][k-512]
__device__ float g_bias[HH];                      // b_ih + b_hh
__device__ float g_h[2][BB * HH];                 // double-buffered hidden state
__device__ float g_hout[(size_t)BB * TT * HH];    // masked hidden outputs (only written where t < len)
__device__ int   g_perm[BB];                      // batch rows sorted by length desc
__device__ int   g_active[TT];                    // active(t) = #{len > t}

// ---------------- prep: counting sort by length (desc) + active counts ----------------
__global__ void prep_sort(const int* __restrict__ lengths) {
    __shared__ int s_len[BB];
    __shared__ int s_hist[TT + 1];
    __shared__ int s_S[TT + 1];     // S[v] = #{len > v}
    __shared__ int s_base[TT + 1];
    int tid = threadIdx.x;          // 512 threads
    if (tid < BB) s_len[tid] = lengths[tid];
    for (int i = tid; i <= TT; i += blockDim.x) s_hist[i] = 0;
    __syncthreads();
    if (tid < BB) atomicAdd(&s_hist[s_len[tid]], 1);
    __syncthreads();
    if (tid == 0) {
        s_S[TT] = 0;
        for (int v = TT - 1; v >= 0; --v) s_S[v] = s_S[v + 1] + s_hist[v + 1];
    }
    __syncthreads();
    for (int i = tid; i <= TT; i += blockDim.x) s_base[i] = s_S[i];
    if (tid < TT) g_active[tid] = s_S[tid];
    __syncthreads();
    if (tid < BB) {
        int pos = atomicAdd(&s_base[s_len[tid]], 1);
        g_perm[pos] = tid;   // sorted desc: prefix of perm is the active set at every t
    }
}

// ---------------- prep: pack W into k-major concat layout, bias, h0 ----------------
__global__ void prep_pack(const float* __restrict__ W_ih, const float* __restrict__ W_hh,
                          const float* __restrict__ b_ih, const float* __restrict__ b_hh,
                          const float* __restrict__ h0) {
    int idx = blockIdx.x * blockDim.x + threadIdx.x;
    int stride = gridDim.x * blockDim.x;
    for (int i = idx; i < KK * HH; i += stride) {
        int k = i / HH, j = i % HH;
        g_W[i] = (k < HH) ? W_hh[(size_t)j * HH + k] : W_ih[(size_t)j * II + (k - HH)];
    }
    for (int i = idx; i < HH; i += stride) g_bias[i] = b_ih[i] + b_hh[i];
    for (int i = idx; i < BB * HH; i += stride) g_h[0][i] = h0[i];
}

// ---------------- one recurrence step: h_new = tanh([h|x] @ Wcat + bias) ----------------
// grid: (HH/JT = 8, BB/ROWS = 32), 256 threads
__global__ __launch_bounds__(STEP_THREADS) void step_kernel(const float* __restrict__ x, int t) {
    int active = g_active[t];
    int r0 = blockIdx.y * ROWS;
    if (r0 >= active) return;
    int nrows = min(ROWS, active - r0);
    int j0 = blockIdx.x * JT;
    int buf = t & 1, nb = buf ^ 1;

    __shared__ float s_hx[ROWS][KK];     // 24 KB
    __shared__ float s_w[KC][JT];        // 16 KB
    __shared__ int   s_rowb[ROWS];

    int tid = threadIdx.x;
    if (tid < ROWS) s_rowb[tid] = (tid < nrows) ? g_perm[r0 + tid] : -1;
    __syncthreads();

    // stage [h | x] rows: warp w loads row w
    {
        int rr = tid >> 5, lane = tid & 31;
        int b = s_rowb[rr];
        const float4* hsrc = (b >= 0) ? (const float4*)&g_h[buf][(size_t)b * HH] : nullptr;
        const float4* xsrc = (b >= 0) ? (const float4*)&x[((size_t)b * TT + t) * II] : nullptr;
        float4* dst = (float4*)&s_hx[rr][0];
        #pragma unroll
        for (int c = lane; c < KK / 4; c += 32) {
            float4 v;
            if (b < 0) { v.x = v.y = v.z = v.w = 0.f; }
            else v = (c < HH / 4) ? hsrc[c] : xsrc[c - HH / 4];
            dst[c] = v;
        }
    }

    float a00 = 0.f, a01 = 0.f, a10 = 0.f, a11 = 0.f;
    int jc = (tid & 31) * 2;   // j pair within tile
    int r  = tid >> 5;         // row (uniform per warp -> smem broadcast for h)

    #pragma unroll 1
    for (int kc = 0; kc < KK; kc += KC) {
        __syncthreads();   // hx ready (first iter) / s_w consumed (later iters)
        // stage W chunk [KC x JT] = 1024 float4 by 256 threads
        {
            const float* gw = &g_W[(size_t)kc * HH + j0];
            #pragma unroll
            for (int q = 0; q < (KC * JT) / (STEP_THREADS * 4); ++q) {
                int p  = tid + q * STEP_THREADS;     // float4 index
                int kk = p / (JT / 4);
                int jj = (p % (JT / 4)) * 4;
                *(float4*)&s_w[kk][jj] = *(const float4*)&gw[(size_t)kk * HH + jj];
            }
        }
        __syncthreads();
        const float4* hp = (const float4*)&s_hx[r][kc];
        #pragma unroll
        for (int k4 = 0; k4 < KC / 4; ++k4) {
            float4 h = hp[k4];
            float2 w0 = *(float2*)&s_w[k4 * 4 + 0][jc];
            float2 w1 = *(float2*)&s_w[k4 * 4 + 1][jc];
            float2 w2 = *(float2*)&s_w[k4 * 4 + 2][jc];
            float2 w3 = *(float2*)&s_w[k4 * 4 + 3][jc];
            a00 = fmaf(h.x, w0.x, a00); a01 = fmaf(h.x, w0.y, a01);
            a10 = fmaf(h.y, w1.x, a10); a11 = fmaf(h.y, w1.y, a11);
            a00 = fmaf(h.z, w2.x, a00); a01 = fmaf(h.z, w2.y, a01);
            a10 = fmaf(h.w, w3.x, a10); a11 = fmaf(h.w, w3.y, a11);
        }
    }

    if (r < nrows) {
        int b = s_rowb[r];
        int j = j0 + jc;
        float v0 = tanhf(a00 + a10 + g_bias[j]);
        float v1 = tanhf(a01 + a11 + g_bias[j + 1]);
        float2 vv = make_float2(v0, v1);
        *(float2*)&g_h[nb][(size_t)b * HH + j] = vv;
        *(float2*)&g_hout[((size_t)b * TT + t) * HH + j] = vv;
    }
}

// ---------------- FC head: out[b,t,:] = W_fc @ hout + b_fc (or b_fc past length) ----------------
__global__ __launch_bounds__(256) void fc_kernel(const int* __restrict__ lengths,
                                                 const float* __restrict__ W_fc,
                                                 const float* __restrict__ b_fc,
                                                 float* __restrict__ out,
                                                 int write_len_tail) {
    __shared__ float s_w[AA][HH];   // 36 KB
    __shared__ float s_b[AA];
    int tid = threadIdx.x;
    for (int i = tid; i < AA * HH; i += 256) s_w[i / HH][i % HH] = W_fc[i];
    if (tid < AA) s_b[tid] = b_fc[tid];
    __syncthreads();

    int lane = tid & 31, wid = tid >> 5;
    int gw = blockIdx.x * 8 + wid;
    int nw = gridDim.x * 8;
    float myb = s_b[lane < AA ? lane : 0];

    for (int item = gw; item < BB * TT; item += nw) {
        int b = item / TT, t = item % TT;
        int len = __ldg(&lengths[b]);
        float res;
        if (t < len) {
            const float4* hp = (const float4*)&g_hout[(size_t)item * HH];
            float4 h[4];
            #pragma unroll
            for (int q = 0; q < 4; ++q) h[q] = hp[q * 32 + lane];   // conflict-free, coalesced
            float myval = 0.f;
            #pragma unroll
            for (int a = 0; a < AA; ++a) {
                const float4* wp = (const float4*)&s_w[a][0];
                float p = 0.f;
                #pragma unroll
                for (int q = 0; q < 4; ++q) {
                    float4 w = wp[q * 32 + lane];
                    p = fmaf(h[q].x, w.x, p); p = fmaf(h[q].y, w.y, p);
                    p = fmaf(h[q].z, w.z, p); p = fmaf(h[q].w, w.w, p);
                }
                p += __shfl_xor_sync(0xFFFFFFFFu, p, 16);
                p += __shfl_xor_sync(0xFFFFFFFFu, p, 8);
                p += __shfl_xor_sync(0xFFFFFFFFu, p, 4);
                p += __shfl_xor_sync(0xFFFFFFFFu, p, 2);
                p += __shfl_xor_sync(0xFFFFFFFFu, p, 1);
                if (lane == a) myval = p;
            }
            res = myval + myb;
        } else {
            res = myb;   // reference: zero hidden past length -> action = b_fc
        }
        if (lane < AA) out[(size_t)item * AA + lane] = res;
    }

    if (write_len_tail && blockIdx.x == 0 && tid < BB) {
        out[(size_t)BB * TT * AA + tid] = (float)__ldg(&lengths[tid]);
    }
}

// ---------------- launch ----------------
extern "C" void kernel_launch(void* const* d_in, const int* in_sizes, int n_in,
                              void* d_out, int out_size) {
    const float* x      = (const float*)d_in[0];
    const float* h0     = (const float*)d_in[1];
    const int*   lengths= (const int*)  d_in[2];
    const float* W_ih   = (const float*)d_in[3];
    const float* W_hh   = (const float*)d_in[4];
    const float* b_ih   = (const float*)d_in[5];
    const float* b_hh   = (const float*)d_in[6];
    const float* W_fc   = (const float*)d_in[7];
    const float* b_fc   = (const float*)d_in[8];
    float* out = (float*)d_out;

    prep_sort<<<1, 512>>>(lengths);
    prep_pack<<<512, 256>>>(W_ih, W_hh, b_ih, b_hh, h0);

    for (int t = 0; t < TT; ++t) {
        step_kernel<<<dim3(HH / JT, BB / ROWS), STEP_THREADS>>>(x, t);
    }

    int tail = (out_size >= BB * TT * AA + BB) ? 1 : 0;
    fc_kernel<<<512, 256>>>(lengths, W_fc, b_fc, out, tail);
}

// round 3
// speedup vs baseline: 2.2706x; 2.2706x over previous
#include <cuda_runtime.h>
#include <math.h>

#define BB 256
#define TT 512
#define II 256
#define HH 512
#define AA 18
#define KK 768          // concat [h | x]
#define NS 4            // k slices
#define KS 192          // k per slice
#define JT 128          // cols per CTA
#define RT 32           // rows per CTA
#define KC 64           // k chunk (double buffered)

// ---------------- scratch ----------------
__device__ float g_W[(size_t)KK * HH];             // [k][j] k<512 -> W_hh[j][k], else W_ih[j][k-512]
__device__ float g_bias[HH];                       // b_ih + b_hh
__device__ float g_part[2][NS][BB][HH];            // per-slice partial pre-activations (sorted-row index)
__device__ float g_hout[(size_t)BB * TT * HH];     // finalized hidden outputs (original b index)
__device__ int   g_perm[BB];
__device__ int   g_active[TT];

// ---------------- cp.async helpers ----------------
__device__ __forceinline__ void cpa16(void* sdst, const void* gsrc) {
    unsigned s = (unsigned)__cvta_generic_to_shared(sdst);
    asm volatile("cp.async.cg.shared.global [%0], [%1], 16;\n" :: "r"(s), "l"(gsrc));
}
#define CPA_COMMIT() asm volatile("cp.async.commit_group;\n" ::: "memory")
#define CPA_WAIT1()  asm volatile("cp.async.wait_group 1;\n" ::: "memory")
#define CPA_WAIT0()  asm volatile("cp.async.wait_group 0;\n" ::: "memory")

// ---------------- prep: counting sort by length (desc) + active counts ----------------
__global__ void prep_sort(const int* __restrict__ lengths) {
    __shared__ int s_len[BB];
    __shared__ int s_hist[TT + 1];
    __shared__ int s_S[TT + 1];
    __shared__ int s_base[TT + 1];
    int tid = threadIdx.x;
    if (tid < BB) s_len[tid] = lengths[tid];
    for (int i = tid; i <= TT; i += blockDim.x) s_hist[i] = 0;
    __syncthreads();
    if (tid < BB) atomicAdd(&s_hist[s_len[tid]], 1);
    __syncthreads();
    if (tid == 0) {
        s_S[TT] = 0;
        for (int v = TT - 1; v >= 0; --v) s_S[v] = s_S[v + 1] + s_hist[v + 1];
    }
    __syncthreads();
    for (int i = tid; i <= TT; i += blockDim.x) s_base[i] = s_S[i];
    if (tid < TT) g_active[tid] = s_S[tid];
    __syncthreads();
    if (tid < BB) {
        int pos = atomicAdd(&s_base[s_len[tid]], 1);
        g_perm[pos] = tid;
    }
}

// ---------------- prep: pack W concat k-major, bias ----------------
__global__ void prep_pack(const float* __restrict__ W_ih, const float* __restrict__ W_hh,
                          const float* __restrict__ b_ih, const float* __restrict__ b_hh) {
    int idx = blockIdx.x * blockDim.x + threadIdx.x;
    int stride = gridDim.x * blockDim.x;
    for (int i = idx; i < KK * HH; i += stride) {
        int k = i / HH, j = i % HH;
        g_W[i] = (k < HH) ? W_hh[(size_t)j * HH + k] : W_ih[(size_t)j * II + (k - HH)];
    }
    for (int i = idx; i < HH; i += stride) g_bias[i] = b_ih[i] + b_hh[i];
}

// ---------------- step kernel ----------------
// kernel(t): stage h_{t-1} from partials (tanh, +g_hout[t-1] writeout), GEMM slice -> partials for h_t.
// t == TT: finalize-only pass (writes g_hout[TT-1]).
// grid: (HH/JT=4, BB/RT=8, NS=4), 256 threads.
__global__ __launch_bounds__(256, 1) void step_kernel(const float* __restrict__ x,
                                                      const float* __restrict__ h0,
                                                      int t) {
    int a_prev = (t == 0) ? BB : g_active[t - 1];
    int r0 = blockIdx.y * RT;
    if (r0 >= a_prev) return;
    int z  = blockIdx.z;
    int cg = blockIdx.x;
    int j0 = cg * JT;
    int tid = threadIdx.x;
    int pbR = (t & 1) ^ 1;   // partials written by step t-1
    int pbW = t & 1;

    __shared__ int s_b[RT];
    if (tid < RT) s_b[tid] = g_perm[r0 + tid];

    // ---- finalize-only pass ----
    if (t == TT) {
        __syncthreads();
        if (cg != 0 || z == 3) return;
        for (int i4 = tid; i4 < RT * (KS / 4); i4 += 256) {
            int rl = i4 / (KS / 4);
            int kl = (i4 % (KS / 4)) * 4;
            int r  = r0 + rl;
            int kg = z * KS + kl;
            if (r >= a_prev || kg >= HH) continue;
            float4 p0 = *(const float4*)&g_part[pbR][0][r][kg];
            float4 p1 = *(const float4*)&g_part[pbR][1][r][kg];
            float4 p2 = *(const float4*)&g_part[pbR][2][r][kg];
            float4 p3 = *(const float4*)&g_part[pbR][3][r][kg];
            float4 v;
            v.x = tanhf(p0.x + p1.x + p2.x + p3.x);
            v.y = tanhf(p0.y + p1.y + p2.y + p3.y);
            v.z = tanhf(p0.z + p1.z + p2.z + p3.z);
            v.w = tanhf(p0.w + p1.w + p2.w + p3.w);
            *(float4*)&g_hout[((size_t)s_b[rl] * TT + (TT - 1)) * HH + kg] = v;
        }
        return;
    }

    extern __shared__ char smem_raw[];
    float (*s_h)[KS]      = (float (*)[KS])smem_raw;                      // 24 KB
    float (*s_w)[KC][JT]  = (float (*)[KC][JT])(smem_raw + RT * KS * 4);  // 2 x 32 KB

    // issue W chunk 0 and 1 loads (cp.async, overlap with staging)
    {
        #pragma unroll
        for (int c = 0; c < 2; ++c) {
            int kb = z * KS + c * KC;
            const float* gw = g_W + (size_t)kb * HH + j0;
            #pragma unroll
            for (int q = 0; q < (KC * JT / 4) / 256; ++q) {   // 8
                int p  = tid + q * 256;
                int kk = p >> 5;
                int jj = (p & 31) * 4;
                cpa16(&s_w[c][kk][jj], gw + (size_t)kk * HH + jj);
            }
            CPA_COMMIT();
        }
    }
    __syncthreads();   // s_b visible

    // ---- stage s_h: h part = tanh(sum of 4 partials [+bias folded in slice0]); x part from gmem ----
    for (int i4 = tid; i4 < RT * (KS / 4); i4 += 256) {
        int rl = i4 / (KS / 4);
        int kl = (i4 % (KS / 4)) * 4;
        int r  = r0 + rl;
        int kg = z * KS + kl;
        float4 v;
        if (r >= a_prev) {
            v.x = v.y = v.z = v.w = 0.f;
        } else if (kg < HH) {
            if (t == 0) {
                v = *(const float4*)&h0[(size_t)s_b[rl] * HH + kg];
            } else {
                float4 p0 = *(const float4*)&g_part[pbR][0][r][kg];
                float4 p1 = *(const float4*)&g_part[pbR][1][r][kg];
                float4 p2 = *(const float4*)&g_part[pbR][2][r][kg];
                float4 p3 = *(const float4*)&g_part[pbR][3][r][kg];
                v.x = tanhf(p0.x + p1.x + p2.x + p3.x);
                v.y = tanhf(p0.y + p1.y + p2.y + p3.y);
                v.z = tanhf(p0.z + p1.z + p2.z + p3.z);
                v.w = tanhf(p0.w + p1.w + p2.w + p3.w);
                if (cg == 0)
                    *(float4*)&g_hout[((size_t)s_b[rl] * TT + (t - 1)) * HH + kg] = v;
            }
        } else {
            v = *(const float4*)&x[((size_t)s_b[rl] * TT + t) * II + (kg - HH)];
        }
        *(float4*)&s_h[rl][kl] = v;
    }
    __syncthreads();   // s_h ready

    // ---- GEMM: 32x128 tile, 4x4 per thread, 3 chunks of KC=64, double-buffered ----
    int ty = tid >> 5;          // 0..7 (row group of 4)
    int tx = tid & 31;          // 0..31 (col group of 4)
    int cb = tx * 4;
    float acc[4][4];
    #pragma unroll
    for (int i = 0; i < 4; ++i)
        #pragma unroll
        for (int jj = 0; jj < 4; ++jj) acc[i][jj] = 0.f;

    #pragma unroll
    for (int c = 0; c < 3; ++c) {
        if (c == 2) { CPA_WAIT0(); } else { CPA_WAIT1(); }
        __syncthreads();   // chunk c ready in s_w[c&1] for all threads
        const float (*wb)[JT] = s_w[c & 1];
        int koff = c * KC;
        #pragma unroll 4
        for (int k4 = 0; k4 < KC / 4; ++k4) {
            float4 hv[4];
            #pragma unroll
            for (int i = 0; i < 4; ++i)
                hv[i] = *(const float4*)&s_h[4 * ty + i][koff + k4 * 4];
            float4 wv[4];
            #pragma unroll
            for (int kk = 0; kk < 4; ++kk)
                wv[kk] = *(const float4*)&wb[k4 * 4 + kk][cb];
            #pragma unroll
            for (int kk = 0; kk < 4; ++kk) {
                float w0 = wv[kk].x, w1 = wv[kk].y, w2 = wv[kk].z, w3 = wv[kk].w;
                #pragma unroll
                for (int i = 0; i < 4; ++i) {
                    float hh = (kk == 0) ? hv[i].x : (kk == 1) ? hv[i].y
                             : (kk == 2) ? hv[i].z : hv[i].w;
                    acc[i][0] = fmaf(hh, w0, acc[i][0]);
                    acc[i][1] = fmaf(hh, w1, acc[i][1]);
                    acc[i][2] = fmaf(hh, w2, acc[i][2]);
                    acc[i][3] = fmaf(hh, w3, acc[i][3]);
                }
            }
        }
        if (c == 0) {   // all threads done reading s_w[0]: refill with chunk 2
            __syncthreads();
            int kb = z * KS + 2 * KC;
            const float* gw = g_W + (size_t)kb * HH + j0;
            #pragma unroll
            for (int q = 0; q < (KC * JT / 4) / 256; ++q) {
                int p  = tid + q * 256;
                int kk = p >> 5;
                int jj = (p & 31) * 4;
                cpa16(&s_w[0][kk][jj], gw + (size_t)kk * HH + jj);
            }
            CPA_COMMIT();
        }
    }

    // ---- epilogue: write slice partials (bias folded into slice 0) ----
    int j = j0 + cb;
    float4 bv;
    if (z == 0) bv = *(const float4*)&g_bias[j];
    #pragma unroll
    for (int i = 0; i < 4; ++i) {
        int r = r0 + 4 * ty + i;
        float4 v = make_float4(acc[i][0], acc[i][1], acc[i][2], acc[i][3]);
        if (z == 0) { v.x += bv.x; v.y += bv.y; v.z += bv.z; v.w += bv.w; }
        *(float4*)&g_part[pbW][z][r][j] = v;
    }
}

// ---------------- FC head ----------------
__global__ __launch_bounds__(256) void fc_kernel(const int* __restrict__ lengths,
                                                 const float* __restrict__ W_fc,
                                                 const float* __restrict__ b_fc,
                                                 float* __restrict__ out,
                                                 int write_len_tail) {
    __shared__ float s_w[AA][HH];
    __shared__ float s_bias[AA];
    int tid = threadIdx.x;
    for (int i = tid; i < AA * HH; i += 256) s_w[i / HH][i % HH] = W_fc[i];
    if (tid < AA) s_bias[tid] = b_fc[tid];
    __syncthreads();

    int lane = tid & 31, wid = tid >> 5;
    int gw = blockIdx.x * 8 + wid;
    int nw = gridDim.x * 8;
    float myb = s_bias[lane < AA ? lane : 0];

    for (int item = gw; item < BB * TT; item += nw) {
        int b = item / TT, t = item % TT;
        int len = __ldg(&lengths[b]);
        float res;
        if (t < len) {
            const float4* hp = (const float4*)&g_hout[(size_t)item * HH];
            float4 h[4];
            #pragma unroll
            for (int q = 0; q < 4; ++q) h[q] = hp[q * 32 + lane];
            float myval = 0.f;
            #pragma unroll
            for (int a = 0; a < AA; ++a) {
                const float4* wp = (const float4*)&s_w[a][0];
                float p = 0.f;
                #pragma unroll
                for (int q = 0; q < 4; ++q) {
                    float4 w = wp[q * 32 + lane];
                    p = fmaf(h[q].x, w.x, p); p = fmaf(h[q].y, w.y, p);
                    p = fmaf(h[q].z, w.z, p); p = fmaf(h[q].w, w.w, p);
                }
                p += __shfl_xor_sync(0xFFFFFFFFu, p, 16);
                p += __shfl_xor_sync(0xFFFFFFFFu, p, 8);
                p += __shfl_xor_sync(0xFFFFFFFFu, p, 4);
                p += __shfl_xor_sync(0xFFFFFFFFu, p, 2);
                p += __shfl_xor_sync(0xFFFFFFFFu, p, 1);
                if (lane == a) myval = p;
            }
            res = myval + myb;
        } else {
            res = myb;
        }
        if (lane < AA) out[(size_t)item * AA + lane] = res;
    }

    if (write_len_tail && blockIdx.x == 0 && tid < BB) {
        out[(size_t)BB * TT * AA + tid] = (float)__ldg(&lengths[tid]);
    }
}

// ---------------- launch ----------------
extern "C" void kernel_launch(void* const* d_in, const int* in_sizes, int n_in,
                              void* d_out, int out_size) {
    const float* x      = (const float*)d_in[0];
    const float* h0     = (const float*)d_in[1];
    const int*   lengths= (const int*)  d_in[2];
    const float* W_ih   = (const float*)d_in[3];
    const float* W_hh   = (const float*)d_in[4];
    const float* b_ih   = (const float*)d_in[5];
    const float* b_hh   = (const float*)d_in[6];
    const float* W_fc   = (const float*)d_in[7];
    const float* b_fc   = (const float*)d_in[8];
    float* out = (float*)d_out;

    const int smem_bytes = RT * KS * 4 + 2 * KC * JT * 4;   // 24KB + 64KB = 90112
    cudaFuncSetAttribute(step_kernel, cudaFuncAttributeMaxDynamicSharedMemorySize, smem_bytes);

    prep_sort<<<1, 512>>>(lengths);
    prep_pack<<<512, 256>>>(W_ih, W_hh, b_ih, b_hh);

    dim3 grid(HH / JT, BB / RT, NS);   // (4, 8, 4) = 128 CTAs
    for (int t = 0; t <= TT; ++t) {
        step_kernel<<<grid, 256, smem_bytes>>>(x, h0, t);
    }

    int tail = (out_size >= BB * TT * AA + BB) ? 1 : 0;
    fc_kernel<<<512, 256>>>(lengths, W_fc, b_fc, out, tail);
}